// round 1
// baseline (speedup 1.0000x reference)
#include <cuda_runtime.h>
#include <cuda_bf16.h>
#include <math.h>

// Problem constants (from reference): N=500000, D=64, A=200000, temperature=1, cross_weight=1
#define DHALF 32              // D/2 float2 lanes
#define WARPS_PER_BLOCK 8
#define MAX_NCE_BLOCKS 65536

__device__ float g_partials[MAX_NCE_BLOCKS];

__device__ __forceinline__ float warp_sum(float v) {
#pragma unroll
    for (int o = 16; o > 0; o >>= 1)
        v += __shfl_xor_sync(0xFFFFFFFFu, v, o);
    return v;
}

__device__ __forceinline__ float softplus_stable(float x) {
    // log(1 + e^x), stable both directions
    return (x > 0.0f) ? (x + log1pf(expf(-x))) : log1pf(expf(x));
}

__device__ __forceinline__ float cos_sim(float dot, float n1sq, float n2sq) {
    float den = sqrtf(n1sq) * sqrtf(n2sq);
    den = fmaxf(den, 1e-8f);
    return dot / den;
}

__global__ __launch_bounds__(256) void mvr_fused_kernel(
    const float* __restrict__ g1, const float* __restrict__ g2,
    const float* __restrict__ s1, const float* __restrict__ s2,
    const float* __restrict__ w,
    const int* __restrict__ aidx, const int* __restrict__ nidx,
    float* __restrict__ out, int N, int A, int embBlocks)
{
    const int warp = threadIdx.x >> 5;
    const int lane = threadIdx.x & 31;

    if ((int)blockIdx.x < embBlocks) {
        // ---------------- Streaming embedding fusion: one warp per row ----------------
        int row = blockIdx.x * WARPS_PER_BLOCK + warp;
        if (row >= N) return;
        size_t base = (size_t)row * 64 + (size_t)lane * 2;

        float2 a = *(const float2*)(g1 + base);
        float2 b = *(const float2*)(g2 + base);
        float2 c = *(const float2*)(s1 + base);
        float2 d = *(const float2*)(s2 + base);

        float2 ga = make_float2(0.5f * (a.x + b.x), 0.5f * (a.y + b.y));
        float2 sa = make_float2(0.5f * (c.x + d.x), 0.5f * (c.y + d.y));

        float2 wg = *(const float2*)(w + lane * 2);
        float2 ws = *(const float2*)(w + 64 + lane * 2);

        float part = ga.x * wg.x + ga.y * wg.y + sa.x * ws.x + sa.y * ws.y;
        part = warp_sum(part);

        float alpha = 1.0f / (1.0f + expf(-part));
        float2 o2 = make_float2(alpha * ga.x + (1.0f - alpha) * sa.x,
                                alpha * ga.y + (1.0f - alpha) * sa.y);
        *(float2*)(out + base) = o2;
    } else {
        // ---------------- InfoNCE: one warp per active item ----------------
        __shared__ float sh[WARPS_PER_BLOCK];
        int nceBlock = blockIdx.x - embBlocks;
        int item = nceBlock * WARPS_PER_BLOCK + warp;

        float loss = 0.0f;
        if (item < A) {
            int ai = aidx[item];
            int ni = nidx[item];
            size_t ba = (size_t)ai * 64 + (size_t)lane * 2;
            size_t bn = (size_t)ni * 64 + (size_t)lane * 2;

            float2 g1a = *(const float2*)(g1 + ba);
            float2 g2a = *(const float2*)(g2 + ba);
            float2 s1a = *(const float2*)(s1 + ba);
            float2 s2a = *(const float2*)(s2 + ba);
            float2 g2n = *(const float2*)(g2 + bn);
            float2 s1n = *(const float2*)(s1 + bn);
            float2 s2n = *(const float2*)(s2 + bn);

            // cross-view averaged vectors
            float2 gav = make_float2(0.5f * (g1a.x + g2a.x), 0.5f * (g1a.y + g2a.y));
            float2 sav = make_float2(0.5f * (s1a.x + s2a.x), 0.5f * (s1a.y + s2a.y));
            float2 snv = make_float2(0.5f * (s1n.x + s2n.x), 0.5f * (s1n.y + s2n.y));

            // 15 partial sums
            float v0  = g1a.x * g2a.x + g1a.y * g2a.y;   // graph pos dot
            float v1  = g1a.x * g1a.x + g1a.y * g1a.y;   // |g1a|^2
            float v2  = g2a.x * g2a.x + g2a.y * g2a.y;   // |g2a|^2
            float v3  = g1a.x * g2n.x + g1a.y * g2n.y;   // graph neg dot
            float v4  = g2n.x * g2n.x + g2n.y * g2n.y;   // |g2n|^2

            float v5  = s1a.x * s2a.x + s1a.y * s2a.y;   // seq pos dot
            float v6  = s1a.x * s1a.x + s1a.y * s1a.y;
            float v7  = s2a.x * s2a.x + s2a.y * s2a.y;
            float v8  = s1a.x * s2n.x + s1a.y * s2n.y;   // seq neg dot
            float v9  = s2n.x * s2n.x + s2n.y * s2n.y;

            float v10 = gav.x * sav.x + gav.y * sav.y;   // cross pos dot
            float v11 = gav.x * gav.x + gav.y * gav.y;
            float v12 = sav.x * sav.x + sav.y * sav.y;
            float v13 = gav.x * snv.x + gav.y * snv.y;   // cross neg dot
            float v14 = snv.x * snv.x + snv.y * snv.y;

            v0 = warp_sum(v0);   v1 = warp_sum(v1);   v2 = warp_sum(v2);
            v3 = warp_sum(v3);   v4 = warp_sum(v4);   v5 = warp_sum(v5);
            v6 = warp_sum(v6);   v7 = warp_sum(v7);   v8 = warp_sum(v8);
            v9 = warp_sum(v9);   v10 = warp_sum(v10); v11 = warp_sum(v11);
            v12 = warp_sum(v12); v13 = warp_sum(v13); v14 = warp_sum(v14);

            float pos_g = cos_sim(v0, v1, v2);
            float neg_g = cos_sim(v3, v1, v4);
            float pos_s = cos_sim(v5, v6, v7);
            float neg_s = cos_sim(v8, v6, v9);
            float pos_c = cos_sim(v10, v11, v12);
            float neg_c = cos_sim(v13, v11, v14);

            loss = softplus_stable(neg_g - pos_g)
                 + softplus_stable(neg_s - pos_s)
                 + softplus_stable(neg_c - pos_c);
        }

        if (lane == 0) sh[warp] = loss;
        __syncthreads();
        if (threadIdx.x == 0) {
            float s = 0.0f;
#pragma unroll
            for (int i = 0; i < WARPS_PER_BLOCK; i++) s += sh[i];
            g_partials[nceBlock] = s;
        }
    }
}

__global__ __launch_bounds__(256) void mvr_finalize_kernel(
    float* __restrict__ out, int nPartials, int A, long long scalarOff)
{
    __shared__ float sh[256];
    float s = 0.0f;
    for (int i = threadIdx.x; i < nPartials; i += 256)
        s += g_partials[i];
    sh[threadIdx.x] = s;
    __syncthreads();
#pragma unroll
    for (int st = 128; st > 0; st >>= 1) {
        if (threadIdx.x < st) sh[threadIdx.x] += sh[threadIdx.x + st];
        __syncthreads();
    }
    if (threadIdx.x == 0)
        out[scalarOff] = sh[0] / (float)A;
}

extern "C" void kernel_launch(void* const* d_in, const int* in_sizes, int n_in,
                              void* d_out, int out_size)
{
    const float* g1 = (const float*)d_in[0];
    const float* g2 = (const float*)d_in[1];
    const float* s1 = (const float*)d_in[2];
    const float* s2 = (const float*)d_in[3];
    const float* w  = (const float*)d_in[4];
    const int* aidx = (const int*)d_in[5];
    const int* nidx = (const int*)d_in[6];
    float* out = (float*)d_out;

    int N = in_sizes[0] / 64;
    int A = in_sizes[5];

    int embBlocks = (N + WARPS_PER_BLOCK - 1) / WARPS_PER_BLOCK;
    int nceBlocks = (A + WARPS_PER_BLOCK - 1) / WARPS_PER_BLOCK;
    if (nceBlocks > MAX_NCE_BLOCKS) nceBlocks = MAX_NCE_BLOCKS; // static scratch bound

    mvr_fused_kernel<<<embBlocks + nceBlocks, 256>>>(
        g1, g2, s1, s2, w, aidx, nidx, out, N, A, embBlocks);

    long long scalarOff = (long long)N * 64;
    mvr_finalize_kernel<<<1, 256>>>(out, nceBlocks, A, scalarOff);
}

// round 2
// speedup vs baseline: 1.2936x; 1.2936x over previous
#include <cuda_runtime.h>
#include <math.h>

// N=500000, D=64, A=200000, temperature=1, cross_weight=1
#define NCE_BLOCKS 2048
#define WPB 8                    // warps per block (256 threads)

__device__ float g_partials[NCE_BLOCKS];
__device__ unsigned int g_count = 0;

__device__ __forceinline__ float dot4(float4 a, float4 b) {
    return a.x * b.x + a.y * b.y + a.z * b.z + a.w * b.w;
}
__device__ __forceinline__ float4 avg4(float4 a, float4 b) {
    return make_float4(0.5f * (a.x + b.x), 0.5f * (a.y + b.y),
                       0.5f * (a.z + b.z), 0.5f * (a.w + b.w));
}
__device__ __forceinline__ float hsum16(float v) {
    // two independent 16-lane reductions per warp (halves don't interact)
#pragma unroll
    for (int o = 8; o > 0; o >>= 1)
        v += __shfl_xor_sync(0xFFFFFFFFu, v, o);
    return v;
}
__device__ __forceinline__ float softplus_stable(float x) {
    return (x > 0.0f) ? (x + log1pf(expf(-x))) : log1pf(expf(x));
}
__device__ __forceinline__ float cos_sim(float dot, float n1sq, float n2sq) {
    float den = sqrtf(n1sq) * sqrtf(n2sq);
    return dot / fmaxf(den, 1e-8f);
}

__global__ __launch_bounds__(256) void mvr_fused_kernel(
    const float* __restrict__ g1, const float* __restrict__ g2,
    const float* __restrict__ s1, const float* __restrict__ s2,
    const float* __restrict__ w,
    const int* __restrict__ aidx, const int* __restrict__ nidx,
    float* __restrict__ out, int N, int A, long long scalarOff)
{
    const int tid  = threadIdx.x;
    const int warp = tid >> 5;
    const int lane = tid & 31;
    const int half = lane >> 4;   // which 16-lane group
    const int l16  = lane & 15;   // lane within group (4 floats each -> D=64)

    if ((int)blockIdx.x >= NCE_BLOCKS) {
        // ---------- Streaming embedding fusion: 16 lanes per row, 2 rows/warp ----------
        int row = ((int)blockIdx.x - NCE_BLOCKS) * (WPB * 2) + warp * 2 + half;
        bool v = row < N;
        size_t base = v ? ((size_t)row * 64 + (size_t)l16 * 4) : 0;

        float4 a = __ldcs((const float4*)(g1 + base));
        float4 b = __ldcs((const float4*)(g2 + base));
        float4 c = __ldcs((const float4*)(s1 + base));
        float4 d = __ldcs((const float4*)(s2 + base));

        float4 ga = avg4(a, b);
        float4 sa = avg4(c, d);

        float4 wg = *(const float4*)(w + l16 * 4);
        float4 ws = *(const float4*)(w + 64 + l16 * 4);

        float part = hsum16(dot4(ga, wg) + dot4(sa, ws));
        float alpha = 1.0f / (1.0f + expf(-part));

        float4 o;
        o.x = fmaf(alpha, ga.x - sa.x, sa.x);
        o.y = fmaf(alpha, ga.y - sa.y, sa.y);
        o.z = fmaf(alpha, ga.z - sa.z, sa.z);
        o.w = fmaf(alpha, ga.w - sa.w, sa.w);
        if (v) __stcs((float4*)(out + base), o);
        return;
    }

    // ---------- InfoNCE: 2 items per warp, grid-stride over A ----------
    __shared__ float sh[WPB];
    __shared__ bool isLast;
    __shared__ float red[256];

    float acc = 0.0f;
    const int stride = NCE_BLOCKS * WPB * 2;
    for (int basei = (int)blockIdx.x * (WPB * 2) + warp * 2; basei < A; basei += stride) {
        int item = basei + half;
        bool v = item < A;
        int ai = v ? aidx[item] : 0;
        int ni = v ? nidx[item] : 0;
        size_t ba = (size_t)ai * 64 + (size_t)l16 * 4;
        size_t bn = (size_t)ni * 64 + (size_t)l16 * 4;

        float4 g1a = *(const float4*)(g1 + ba);
        float4 g2a = *(const float4*)(g2 + ba);
        float4 s1a = *(const float4*)(s1 + ba);
        float4 s2a = *(const float4*)(s2 + ba);
        float4 g2n = *(const float4*)(g2 + bn);
        float4 s1n = *(const float4*)(s1 + bn);
        float4 s2n = *(const float4*)(s2 + bn);

        float4 gav = avg4(g1a, g2a);
        float4 sav = avg4(s1a, s2a);
        float4 snv = avg4(s1n, s2n);

        float v0  = hsum16(dot4(g1a, g2a));
        float v1  = hsum16(dot4(g1a, g1a));
        float v2  = hsum16(dot4(g2a, g2a));
        float v3  = hsum16(dot4(g1a, g2n));
        float v4  = hsum16(dot4(g2n, g2n));
        float v5  = hsum16(dot4(s1a, s2a));
        float v6  = hsum16(dot4(s1a, s1a));
        float v7  = hsum16(dot4(s2a, s2a));
        float v8  = hsum16(dot4(s1a, s2n));
        float v9  = hsum16(dot4(s2n, s2n));
        float v10 = hsum16(dot4(gav, sav));
        float v11 = hsum16(dot4(gav, gav));
        float v12 = hsum16(dot4(sav, sav));
        float v13 = hsum16(dot4(gav, snv));
        float v14 = hsum16(dot4(snv, snv));

        float loss = softplus_stable(cos_sim(v3,  v1,  v4)  - cos_sim(v0,  v1,  v2))
                   + softplus_stable(cos_sim(v8,  v6,  v9)  - cos_sim(v5,  v6,  v7))
                   + softplus_stable(cos_sim(v13, v11, v14) - cos_sim(v10, v11, v12));
        acc += v ? loss : 0.0f;
    }

    // combine the two half-warp accumulators (all lanes in a half hold same acc)
    float tot = acc + __shfl_xor_sync(0xFFFFFFFFu, acc, 16);
    if (lane == 0) sh[warp] = tot;
    __syncthreads();

    if (tid == 0) {
        float s = 0.0f;
#pragma unroll
        for (int i = 0; i < WPB; i++) s += sh[i];
        g_partials[blockIdx.x] = s;
        __threadfence();
        unsigned t = atomicAdd(&g_count, 1u);
        isLast = (t == NCE_BLOCKS - 1);
    }
    __syncthreads();

    if (isLast) {
        __threadfence();
        float s = 0.0f;
        for (int i = tid; i < NCE_BLOCKS; i += 256)
            s += g_partials[i];
        red[tid] = s;
        __syncthreads();
#pragma unroll
        for (int st = 128; st > 0; st >>= 1) {
            if (tid < st) red[tid] += red[tid + st];
            __syncthreads();
        }
        if (tid == 0) {
            out[scalarOff] = red[0] / (float)A;
            g_count = 0;   // reset for next graph replay (deterministic)
        }
    }
}

extern "C" void kernel_launch(void* const* d_in, const int* in_sizes, int n_in,
                              void* d_out, int out_size)
{
    const float* g1 = (const float*)d_in[0];
    const float* g2 = (const float*)d_in[1];
    const float* s1 = (const float*)d_in[2];
    const float* s2 = (const float*)d_in[3];
    const float* w  = (const float*)d_in[4];
    const int* aidx = (const int*)d_in[5];
    const int* nidx = (const int*)d_in[6];
    float* out = (float*)d_out;

    int N = in_sizes[0] / 64;
    int A = in_sizes[5];

    int embBlocks = (N + WPB * 2 - 1) / (WPB * 2);
    long long scalarOff = (long long)N * 64;

    mvr_fused_kernel<<<NCE_BLOCKS + embBlocks, 256>>>(
        g1, g2, s1, s2, w, aidx, nidx, out, N, A, scalarOff);
}

// round 3
// speedup vs baseline: 1.3865x; 1.0718x over previous
#include <cuda_runtime.h>
#include <math.h>

// N=500000, D=64, A=200000, temperature=1, cross_weight=1
#define NCE_BLOCKS 2048
#define WPB 8                    // warps per block (256 threads)

__device__ float g_partials[NCE_BLOCKS];
__device__ unsigned int g_count = 0;

__device__ __forceinline__ float dot4(float4 a, float4 b) {
    return a.x * b.x + a.y * b.y + a.z * b.z + a.w * b.w;
}
__device__ __forceinline__ float4 avg4(float4 a, float4 b) {
    return make_float4(0.5f * (a.x + b.x), 0.5f * (a.y + b.y),
                       0.5f * (a.z + b.z), 0.5f * (a.w + b.w));
}
__device__ __forceinline__ float hsum16(float v) {
#pragma unroll
    for (int o = 8; o > 0; o >>= 1)
        v += __shfl_xor_sync(0xFFFFFFFFu, v, o);
    return v;
}
__device__ __forceinline__ float softplus_stable(float x) {
    return (x > 0.0f) ? (x + log1pf(expf(-x))) : log1pf(expf(x));
}
__device__ __forceinline__ float cos_sim(float dot, float n1sq, float n2sq) {
    float den = sqrtf(n1sq) * sqrtf(n2sq);
    return dot / fmaxf(den, 1e-8f);
}

__global__ __launch_bounds__(256, 5) void mvr_fused_kernel(
    const float* __restrict__ g1, const float* __restrict__ g2,
    const float* __restrict__ s1, const float* __restrict__ s2,
    const float* __restrict__ w,
    const int* __restrict__ aidx, const int* __restrict__ nidx,
    float* __restrict__ out, int N, int A, int scalarOff)
{
    const int tid  = threadIdx.x;
    const int warp = tid >> 5;
    const int lane = tid & 31;
    const int half = lane >> 4;   // which 16-lane group
    const int l16  = lane & 15;   // lane within group (4 floats -> D=64)

    if ((int)blockIdx.x >= NCE_BLOCKS) {
        // ---------- Streaming embedding fusion: 16 lanes per row, 2 rows/warp ----------
        int row = ((int)blockIdx.x - NCE_BLOCKS) * (WPB * 2) + warp * 2 + half;
        bool v = row < N;
        unsigned base = v ? ((unsigned)row * 64u + (unsigned)l16 * 4u) : 0u;

        float4 a = __ldcs((const float4*)(g1 + base));
        float4 b = __ldcs((const float4*)(g2 + base));
        float4 c = __ldcs((const float4*)(s1 + base));
        float4 d = __ldcs((const float4*)(s2 + base));

        float4 ga = avg4(a, b);
        float4 sa = avg4(c, d);

        float4 wg = *(const float4*)(w + l16 * 4);
        float4 ws = *(const float4*)(w + 64 + l16 * 4);

        float part = hsum16(dot4(ga, wg) + dot4(sa, ws));
        float alpha = 1.0f / (1.0f + expf(-part));

        float4 o;
        o.x = fmaf(alpha, ga.x - sa.x, sa.x);
        o.y = fmaf(alpha, ga.y - sa.y, sa.y);
        o.z = fmaf(alpha, ga.z - sa.z, sa.z);
        o.w = fmaf(alpha, ga.w - sa.w, sa.w);
        if (v) __stcs((float4*)(out + base), o);
        return;
    }

    // ---------- InfoNCE: 2 items per warp (16 lanes each), grid-stride ----------
    __shared__ float sh[WPB];
    __shared__ bool isLast;
    __shared__ float red[256];

    float acc = 0.0f;
    const int stride = NCE_BLOCKS * WPB * 2;
    int item0 = (int)blockIdx.x * (WPB * 2) + warp * 2 + half;

    // prefetch first indices
    bool v = item0 < A;
    int ai = v ? __ldcs(aidx + item0) : 0;
    int ni = v ? __ldcs(nidx + item0) : 0;

    for (int item = item0; item < A + half; item += stride) {  // loop while this half may be valid
        unsigned ba = (unsigned)ai * 64u + (unsigned)l16 * 4u;
        unsigned bn = (unsigned)ni * 64u + (unsigned)l16 * 4u;

        float4 g1a = *(const float4*)(g1 + ba);
        float4 g2a = *(const float4*)(g2 + ba);
        float4 g2n = *(const float4*)(g2 + bn);
        float4 s1a = *(const float4*)(s1 + ba);
        float4 s2a = *(const float4*)(s2 + ba);
        float4 s1n = *(const float4*)(s1 + bn);
        float4 s2n = *(const float4*)(s2 + bn);

        // prefetch next iteration's indices early
        int nitem = item + stride;
        bool nv = nitem < A;
        int nai = nv ? __ldcs(aidx + nitem) : 0;
        int nni = nv ? __ldcs(nidx + nitem) : 0;

        float4 snv = avg4(s1n, s2n);           // s1n/s2n die here
        float4 gav = avg4(g1a, g2a);
        float4 sav = avg4(s1a, s2a);

        float v0  = hsum16(dot4(g1a, g2a));
        float v1  = hsum16(dot4(g1a, g1a));
        float v2  = hsum16(dot4(g2a, g2a));
        float v3  = hsum16(dot4(g1a, g2n));
        float v4  = hsum16(dot4(g2n, g2n));
        float v5  = hsum16(dot4(s1a, s2a));
        float v6  = hsum16(dot4(s1a, s1a));
        float v7  = hsum16(dot4(s2a, s2a));
        float v8  = hsum16(dot4(s1a, s2n));
        float v9  = hsum16(dot4(s2n, s2n));
        float v10 = hsum16(dot4(gav, sav));
        float v11 = hsum16(dot4(gav, gav));
        float v12 = hsum16(dot4(sav, sav));
        float v13 = hsum16(dot4(gav, snv));
        float v14 = hsum16(dot4(snv, snv));

        float loss = softplus_stable(cos_sim(v3,  v1,  v4)  - cos_sim(v0,  v1,  v2))
                   + softplus_stable(cos_sim(v8,  v6,  v9)  - cos_sim(v5,  v6,  v7))
                   + softplus_stable(cos_sim(v13, v11, v14) - cos_sim(v10, v11, v12));
        acc += (item < A) ? loss : 0.0f;

        ai = nai; ni = nni;
    }

    // combine the two half-warp accumulators
    float tot = acc + __shfl_xor_sync(0xFFFFFFFFu, acc, 16);
    if (lane == 0) sh[warp] = tot;
    __syncthreads();

    if (tid == 0) {
        float s = 0.0f;
#pragma unroll
        for (int i = 0; i < WPB; i++) s += sh[i];
        g_partials[blockIdx.x] = s;
        __threadfence();
        unsigned t = atomicAdd(&g_count, 1u);
        isLast = (t == NCE_BLOCKS - 1);
    }
    __syncthreads();

    if (isLast) {
        __threadfence();
        float s = 0.0f;
        for (int i = tid; i < NCE_BLOCKS; i += 256)
            s += g_partials[i];
        red[tid] = s;
        __syncthreads();
#pragma unroll
        for (int st = 128; st > 0; st >>= 1) {
            if (tid < st) red[tid] += red[tid + st];
            __syncthreads();
        }
        if (tid == 0) {
            out[scalarOff] = red[0] / (float)A;
            g_count = 0;   // reset for next graph replay
        }
    }
}

extern "C" void kernel_launch(void* const* d_in, const int* in_sizes, int n_in,
                              void* d_out, int out_size)
{
    const float* g1 = (const float*)d_in[0];
    const float* g2 = (const float*)d_in[1];
    const float* s1 = (const float*)d_in[2];
    const float* s2 = (const float*)d_in[3];
    const float* w  = (const float*)d_in[4];
    const int* aidx = (const int*)d_in[5];
    const int* nidx = (const int*)d_in[6];
    float* out = (float*)d_out;

    int N = in_sizes[0] / 64;
    int A = in_sizes[5];

    int embBlocks = (N + WPB * 2 - 1) / (WPB * 2);
    int scalarOff = N * 64;   // 32,000,000 fits in int

    mvr_fused_kernel<<<NCE_BLOCKS + embBlocks, 256>>>(
        g1, g2, s1, s2, w, aidx, nidx, out, N, A, scalarOff);
}

// round 5
// speedup vs baseline: 1.4163x; 1.0215x over previous
#include <cuda_runtime.h>
#include <math.h>

// N=500000, D=64, A=200000, temperature=1, cross_weight=1
#define NCE_BLOCKS 2048
#define WPB 8                    // warps per block (256 threads)

__device__ float g_partials[NCE_BLOCKS];
__device__ unsigned int g_count = 0;

__device__ __forceinline__ float dot4(float4 a, float4 b) {
    return a.x * b.x + a.y * b.y + a.z * b.z + a.w * b.w;
}
__device__ __forceinline__ float4 avg4(float4 a, float4 b) {
    return make_float4(0.5f * (a.x + b.x), 0.5f * (a.y + b.y),
                       0.5f * (a.z + b.z), 0.5f * (a.w + b.w));
}
__device__ __forceinline__ float hsum16(float v) {
#pragma unroll
    for (int o = 8; o > 0; o >>= 1)
        v += __shfl_xor_sync(0xFFFFFFFFu, v, o);
    return v;
}
__device__ __forceinline__ float softplus_stable(float x) {
    return (x > 0.0f) ? (x + log1pf(expf(-x))) : log1pf(expf(x));
}
__device__ __forceinline__ float cos_sim(float dot, float n1sq, float n2sq) {
    float den = sqrtf(n1sq) * sqrtf(n2sq);
    return dot / fmaxf(den, 1e-8f);
}
__device__ __forceinline__ float4 ldcg4(const float* p) {
    return __ldcg((const float4*)p);
}

__global__ __launch_bounds__(256, 6) void mvr_fused_kernel(
    const float* __restrict__ g1, const float* __restrict__ g2,
    const float* __restrict__ s1, const float* __restrict__ s2,
    const float* __restrict__ w,
    const int* __restrict__ aidx, const int* __restrict__ nidx,
    float* __restrict__ out, int N, int A, int scalarOff)
{
    const int tid  = threadIdx.x;
    const int warp = tid >> 5;
    const int lane = tid & 31;
    const int half = lane >> 4;   // which 16-lane group
    const int l16  = lane & 15;   // lane within group (4 floats -> D=64)

    if ((int)blockIdx.x >= NCE_BLOCKS) {
        // ---------- Streaming embedding fusion: 16 lanes per row, 2 rows/warp ----------
        int row = ((int)blockIdx.x - NCE_BLOCKS) * (WPB * 2) + warp * 2 + half;
        bool v = row < N;
        unsigned base = v ? ((unsigned)row * 64u + (unsigned)l16 * 4u) : 0u;

        float4 a = __ldcs((const float4*)(g1 + base));
        float4 b = __ldcs((const float4*)(g2 + base));
        float4 c = __ldcs((const float4*)(s1 + base));
        float4 d = __ldcs((const float4*)(s2 + base));

        float4 ga = avg4(a, b);
        float4 sa = avg4(c, d);

        float4 wg = *(const float4*)(w + l16 * 4);
        float4 ws = *(const float4*)(w + 64 + l16 * 4);

        float part = hsum16(dot4(ga, wg) + dot4(sa, ws));
        float alpha = 1.0f / (1.0f + expf(-part));

        float4 o;
        o.x = fmaf(alpha, ga.x - sa.x, sa.x);
        o.y = fmaf(alpha, ga.y - sa.y, sa.y);
        o.z = fmaf(alpha, ga.z - sa.z, sa.z);
        o.w = fmaf(alpha, ga.w - sa.w, sa.w);
        if (v) __stcs((float4*)(out + base), o);
        return;
    }

    // ---------- InfoNCE: 2 items per warp (16 lanes each), grid-stride ----------
    __shared__ float sh[WPB];
    __shared__ bool isLast;
    __shared__ float red[256];

    float acc = 0.0f;
    const int stride = NCE_BLOCKS * WPB * 2;
    int item0 = (int)blockIdx.x * (WPB * 2) + warp * 2 + half;

#pragma unroll 1
    for (int item = item0; item < A + half; item += stride) {
        bool valid = item < A;
        int it = valid ? item : 0;
        int ai = __ldg(aidx + it);
        int ni = __ldg(nidx + it);
        unsigned ba = (unsigned)ai * 64u + (unsigned)l16 * 4u;
        unsigned bn = (unsigned)ni * 64u + (unsigned)l16 * 4u;

        // all 7 row loads issued up front for MLP
        float4 g1a = ldcg4(g1 + ba);
        float4 g2a = ldcg4(g2 + ba);
        float4 g2n = ldcg4(g2 + bn);
        float4 s1a = ldcg4(s1 + ba);
        float4 s2a = ldcg4(s2 + ba);
        float4 s1n = ldcg4(s1 + bn);
        float4 s2n = ldcg4(s2 + bn);

        // graph view: consume g2n early
        float v0 = hsum16(dot4(g1a, g2a));
        float v1 = hsum16(dot4(g1a, g1a));
        float v2 = hsum16(dot4(g2a, g2a));
        float v3 = hsum16(dot4(g1a, g2n));
        float v4 = hsum16(dot4(g2n, g2n));       // g2n dead
        float4 gav = avg4(g1a, g2a);             // g1a,g2a -> gav

        // sequence view: consume s1n into snv immediately
        float4 snv = avg4(s1n, s2n);             // s1n dead
        float v5 = hsum16(dot4(s1a, s2a));
        float v6 = hsum16(dot4(s1a, s1a));
        float v7 = hsum16(dot4(s2a, s2a));
        float v8 = hsum16(dot4(s1a, s2n));
        float v9 = hsum16(dot4(s2n, s2n));       // s2n dead
        float4 sav = avg4(s1a, s2a);             // s1a,s2a -> sav

        // cross view
        float v10 = hsum16(dot4(gav, sav));
        float v11 = hsum16(dot4(gav, gav));
        float v12 = hsum16(dot4(sav, sav));
        float v13 = hsum16(dot4(gav, snv));
        float v14 = hsum16(dot4(snv, snv));

        float loss = softplus_stable(cos_sim(v3,  v1,  v4)  - cos_sim(v0,  v1,  v2))
                   + softplus_stable(cos_sim(v8,  v6,  v9)  - cos_sim(v5,  v6,  v7))
                   + softplus_stable(cos_sim(v13, v11, v14) - cos_sim(v10, v11, v12));
        acc += valid ? loss : 0.0f;
    }

    // combine the two half-warp accumulators
    float tot = acc + __shfl_xor_sync(0xFFFFFFFFu, acc, 16);
    if (lane == 0) sh[warp] = tot;
    __syncthreads();

    if (tid == 0) {
        float s = 0.0f;
#pragma unroll
        for (int i = 0; i < WPB; i++) s += sh[i];
        g_partials[blockIdx.x] = s;
        __threadfence();
        unsigned t = atomicAdd(&g_count, 1u);
        isLast = (t == NCE_BLOCKS - 1);
    }
    __syncthreads();

    if (isLast) {
        __threadfence();
        float s = 0.0f;
        for (int i = tid; i < NCE_BLOCKS; i += 256)
            s += g_partials[i];
        red[tid] = s;
        __syncthreads();
#pragma unroll
        for (int st = 128; st > 0; st >>= 1) {
            if (tid < st) red[tid] += red[tid + st];
            __syncthreads();
        }
        if (tid == 0) {
            out[scalarOff] = red[0] / (float)A;
            g_count = 0;   // reset for next graph replay
        }
    }
}

extern "C" void kernel_launch(void* const* d_in, const int* in_sizes, int n_in,
                              void* d_out, int out_size)
{
    const float* g1 = (const float*)d_in[0];
    const float* g2 = (const float*)d_in[1];
    const float* s1 = (const float*)d_in[2];
    const float* s2 = (const float*)d_in[3];
    const float* w  = (const float*)d_in[4];
    const int* aidx = (const int*)d_in[5];
    const int* nidx = (const int*)d_in[6];
    float* out = (float*)d_out;

    int N = in_sizes[0] / 64;
    int A = in_sizes[5];

    int embBlocks = (N + WPB * 2 - 1) / (WPB * 2);
    int scalarOff = N * 64;   // 32,000,000 fits in int

    mvr_fused_kernel<<<NCE_BLOCKS + embBlocks, 256>>>(
        g1, g2, s1, s2, w, aidx, nidx, out, N, A, scalarOff);
}